// round 15
// baseline (speedup 1.0000x reference)
#include <cuda_runtime.h>
#include <cuda_bf16.h>
#include <stdint.h>
#include <math.h>
#include <string.h>

// ---------------- problem constants ----------------
#define M_DIM 32768
#define N_DIM 1024
#define K_DIM 1024

#define BM 128
#define BN 256
#define BK 64
#define STAGES 4
#define KT_TOTAL 48                        // 3 segments * (1024/64)
#define A_BYTES (BM * 128)                 // 16 KB
#define B_BYTES (BN * 128)                 // 32 KB
#define STAGE_BYTES (A_BYTES + B_BYTES)    // 48 KB
#define SMEM_BYTES (STAGES * STAGE_BYTES)  // 192 KB

// ---------------- scratch (static device allocations) ----------------
__device__ __nv_bfloat16 g_xh[(size_t)M_DIM * K_DIM];
__device__ __nv_bfloat16 g_xl[(size_t)M_DIM * K_DIM];
__device__ __nv_bfloat16 g_wh[(size_t)N_DIM * K_DIM];
__device__ __nv_bfloat16 g_wl[(size_t)N_DIM * K_DIM];

// NF5 tables, host-computed, passed by value (256 B kernel param)
struct NF5Tab {
    float    bnd[32];   // 31 boundaries + +inf guard
    uint32_t prs[32];   // per level: bf16(level) | bf16(level - bf16(level)) << 16
};

// ---------------- quantize (R12 verbatim: blockwise NF5, hi/lo bf16 split) ----
// thread = 8 consecutive elems; 4-lane subgroup = one 32-elem block.
// Grid sizes divide the element count so every lane iterates every pass
// (redux.sync needs full-group participation).
__global__ void __launch_bounds__(256)
quant_kernel(const NF5Tab tab, const float4* __restrict__ in,
             uint4* __restrict__ hi, uint4* __restrict__ lo, int n8) {
    __shared__ float sthr[1025];
    __shared__ uint32_t sprs[2050];         // [2*key + sel] -> lh | ll<<16 (bf16 bits)
    for (int j = threadIdx.x; j < 1025; j += blockDim.x) {
        float left = (float)j * (1.0f / 512.0f) - 1.0f;
        int idx0 = 0;
#pragma unroll
        for (int i = 0; i < 31; i++) idx0 += (tab.bnd[i] < left) ? 1 : 0;
        int idx1 = (idx0 < 31) ? idx0 + 1 : 31;
        sthr[j] = tab.bnd[idx0];
        sprs[2 * j]     = tab.prs[idx0];
        sprs[2 * j + 1] = tab.prs[idx1];
    }
    __syncthreads();

    const uint32_t gmask = 0xFu << (threadIdx.x & 28u);  // 4-lane group mask
    const int stride = gridDim.x * blockDim.x;
    for (int gid = blockIdx.x * blockDim.x + threadIdx.x; gid < n8; gid += stride) {
        float4 v0 = __ldcs(in + 2 * (size_t)gid);
        float4 v1 = __ldcs(in + 2 * (size_t)gid + 1);
        float vv[8] = {v0.x, v0.y, v0.z, v0.w, v1.x, v1.y, v1.z, v1.w};
        // amax via uint-max on |bits| (positive floats order-isomorphic to uints)
        uint32_t ab = 0;
#pragma unroll
        for (int t = 0; t < 8; t++)
            ab = max(ab, __float_as_uint(vv[t]) & 0x7fffffffu);
        uint32_t rb;
        asm volatile("redux.sync.max.u32 %0, %1, %2;" : "=r"(rb) : "r"(ab), "r"(gmask));
        float am = fmaxf(__uint_as_float(rb), 1e-12f);
        // exact ceil(log2(am)) via exponent bits (am normal, positive)
        uint32_t amb = __float_as_uint(am);
        int E = (int)(amb >> 23) - 127;
        int ce = ((amb & 0x7fffffu) != 0u) ? E + 1 : E;
        float inv = __uint_as_float((uint32_t)(127 - ce) << 23);
        // power-of-2 scale as packed bf16x2 (exactly representable)
        uint32_t scb = (uint32_t)__bfloat16_as_ushort(
            __float2bfloat16(__uint_as_float((uint32_t)(ce + 127) << 23)));
        uint32_t scpack = scb | (scb << 16);

        uint32_t q[8];   // packed (h = low16, l = high16) per element
#pragma unroll
        for (int t = 0; t < 8; t++) {
            float nrm = vv[t] * inv;                       // exact (pow2)
            int key = (int)fmaf(nrm, 512.0f, 512.0f);      // == (nrm+1)*512 bit-exact
            int sel = (sthr[key] < nrm) ? 1 : 0;
            uint32_t pr = sprs[2 * key + sel];
            // level * scale in bf16x2: both mults exact (bf16 level x pow2 scale)
            asm("mul.bf16x2 %0, %1, %2;" : "=r"(q[t]) : "r"(pr), "r"(scpack));
        }
        uint4 hv, lv;
        asm("prmt.b32 %0, %1, %2, 0x5410;" : "=r"(hv.x) : "r"(q[0]), "r"(q[1]));
        asm("prmt.b32 %0, %1, %2, 0x5410;" : "=r"(hv.y) : "r"(q[2]), "r"(q[3]));
        asm("prmt.b32 %0, %1, %2, 0x5410;" : "=r"(hv.z) : "r"(q[4]), "r"(q[5]));
        asm("prmt.b32 %0, %1, %2, 0x5410;" : "=r"(hv.w) : "r"(q[6]), "r"(q[7]));
        asm("prmt.b32 %0, %1, %2, 0x7632;" : "=r"(lv.x) : "r"(q[0]), "r"(q[1]));
        asm("prmt.b32 %0, %1, %2, 0x7632;" : "=r"(lv.y) : "r"(q[2]), "r"(q[3]));
        asm("prmt.b32 %0, %1, %2, 0x7632;" : "=r"(lv.z) : "r"(q[4]), "r"(q[5]));
        asm("prmt.b32 %0, %1, %2, 0x7632;" : "=r"(lv.w) : "r"(q[6]), "r"(q[7]));
        __stcs(hi + gid, hv);
        __stcs(lo + gid, lv);
    }
}

// ---------------- GEMM: 16 warps of 64x32 (4 warps/SMSP) ----------------
// CTA 128x256, 512 threads, BK=64, 4 stages (192 KB smem), R8 pipeline order.
__device__ __forceinline__ uint32_t smem_u32(const void* p) {
    uint32_t a;
    asm("{ .reg .u64 t; cvta.to.shared.u64 t, %1; cvt.u32.u64 %0, t; }" : "=r"(a) : "l"(p));
    return a;
}
__device__ __forceinline__ void cpa16(uint32_t dst, const void* src) {
    asm volatile("cp.async.cg.shared.global [%0], [%1], 16;\n" :: "r"(dst), "l"(src));
}
__device__ __forceinline__ void ldsm4(uint32_t* r, uint32_t addr) {
    asm volatile("ldmatrix.sync.aligned.m8n8.x4.shared.b16 {%0,%1,%2,%3}, [%4];\n"
                 : "=r"(r[0]), "=r"(r[1]), "=r"(r[2]), "=r"(r[3]) : "r"(addr));
}

#define MMA_BF16(d, a0, a1, a2, a3, b0, b1)                                      \
    asm volatile(                                                                \
        "mma.sync.aligned.m16n8k16.row.col.f32.bf16.bf16.f32 "                   \
        "{%0,%1,%2,%3}, {%4,%5,%6,%7}, {%8,%9}, {%0,%1,%2,%3};\n"                \
        : "+f"(d[0]), "+f"(d[1]), "+f"(d[2]), "+f"(d[3])                         \
        : "r"(a0), "r"(a1), "r"(a2), "r"(a3), "r"(b0), "r"(b1))

__global__ void __launch_bounds__(512, 1)
gemm_kernel(const float* __restrict__ bias, float* __restrict__ out) {
    extern __shared__ __align__(1024) char smem[];
    const uint32_t sb = smem_u32(smem);
    const int tid  = threadIdx.x;
    const int lane = tid & 31, wid = tid >> 5;
    const int m0 = blockIdx.y * BM;
    const int n0 = blockIdx.x * BN;
    const int wm = (wid >> 3) * 64;     // warp m offset (2 warps in m)
    const int wn = (wid & 7) * 32;      // warp n offset (8 warps in n)
    const int l15 = lane & 15, lh4 = lane >> 4;

    float acc[4][4][4];
#pragma unroll
    for (int i = 0; i < 4; i++)
#pragma unroll
        for (int j = 0; j < 4; j++)
#pragma unroll
            for (int k = 0; k < 4; k++) acc[i][j][k] = 0.0f;

    uint32_t af[2][4][4], bf[2][2][4];   // double-buffered fragments

    // stage loader: 16B cp.async, XOR-swizzled 128B rows. One commit per call.
    auto load_stage = [&](int tile, int s) {
        const int seg = tile >> 4;
        const int k0  = (tile & 15) * 64;
        const __nv_bfloat16* Ab = (seg == 1) ? g_xl : g_xh;
        const __nv_bfloat16* Bb = (seg == 2) ? g_wl : g_wh;
        const uint32_t stA = sb + s * STAGE_BYTES;
        const uint32_t stB = stA + A_BYTES;
        // A: 128 rows x 8 chunks = 1024 -> 2 per thread (512 threads)
#pragma unroll
        for (int q = 0; q < 2; q++) {
            int idx = tid + q * 512;
            int row = idx >> 3, ch = idx & 7;
            int sw = ch ^ (row & 7);
            cpa16(stA + row * 128 + sw * 16,
                  Ab + (size_t)(m0 + row) * K_DIM + k0 + ch * 8);
        }
        // B: 256 rows x 8 chunks = 2048 -> 4 per thread
#pragma unroll
        for (int q = 0; q < 4; q++) {
            int idx = tid + q * 512;
            int row = idx >> 3, ch = idx & 7;
            int sw = ch ^ (row & 7);
            cpa16(stB + row * 128 + sw * 16,
                  Bb + (size_t)(n0 + row) * K_DIM + k0 + ch * 8);
        }
        asm volatile("cp.async.commit_group;\n" ::);
    };

    // fragment loader for one k16 slice (kf) of a stage
    auto ldsm_frags = [&](uint32_t (*A)[4], uint32_t (*B)[4], uint32_t stA, int kf) {
        const uint32_t stB = stA + A_BYTES;
        const int ch = kf * 2 + lh4;
#pragma unroll
        for (int mf = 0; mf < 4; mf++) {
            int row = wm + mf * 16 + l15;
            ldsm4(A[mf], stA + row * 128 + ((ch ^ (row & 7)) * 16));
        }
#pragma unroll
        for (int p = 0; p < 2; p++) {
            int row = wn + p * 16 + l15;
            ldsm4(B[p], stB + row * 128 + ((ch ^ (row & 7)) * 16));
        }
    };

    // prologue: stages 0,1,2 in flight; wait stage 0 landed; preload kf0 frags
    load_stage(0, 0);
    load_stage(1, 1);
    load_stage(2, 2);
    asm volatile("cp.async.wait_group 2;\n" ::);
    __syncthreads();
    ldsm_frags(af[0], bf[0], sb, 0);

#pragma unroll 1
    for (int t = 0; t < KT_TOTAL; t++) {
        const uint32_t stA = sb + (t & 3) * STAGE_BYTES;
#pragma unroll
        for (int kf = 0; kf < 4; kf++) {
            const int cur = kf & 1, nxt = cur ^ 1;
            if (kf < 3) {
                ldsm_frags(af[nxt], bf[nxt], stA, kf + 1);
            } else {
                // stage t+1 was committed two tiles ago -> wait is a no-op;
                // the newest group (t+2's load) may stay in flight.
                asm volatile("cp.async.wait_group 1;\n" ::);
                __syncthreads();
                int nt = t + 3;
                if (nt < KT_TOTAL) load_stage(nt, nt & 3);
                else asm volatile("cp.async.commit_group;\n" ::);
                if (t + 1 < KT_TOTAL)
                    ldsm_frags(af[nxt], bf[nxt],
                               sb + ((t + 1) & 3) * STAGE_BYTES, 0);
            }
#pragma unroll
            for (int mf = 0; mf < 4; mf++) {
#pragma unroll
                for (int nf = 0; nf < 4; nf++) {
                    uint32_t b0 = bf[cur][nf >> 1][nf & 1];
                    uint32_t b1 = bf[cur][nf >> 1][(nf & 1) + 2];
                    MMA_BF16(acc[mf][nf], af[cur][mf][0], af[cur][mf][1],
                             af[cur][mf][2], af[cur][mf][3], b0, b1);
                }
            }
        }
    }

    // epilogue: + bias, f32 out
    const int r  = lane >> 2;
    const int c2 = (lane & 3) * 2;
#pragma unroll
    for (int nf = 0; nf < 4; nf++) {
        int col = n0 + wn + nf * 8 + c2;
        float b0 = __ldg(bias + col);
        float b1 = __ldg(bias + col + 1);
#pragma unroll
        for (int mf = 0; mf < 4; mf++) {
            int row0 = m0 + wm + mf * 16 + r;
            float2 v0 = make_float2(acc[mf][nf][0] + b0, acc[mf][nf][1] + b1);
            float2 v1 = make_float2(acc[mf][nf][2] + b0, acc[mf][nf][3] + b1);
            *(float2*)(out + (size_t)row0 * N_DIM + col) = v0;
            *(float2*)(out + (size_t)(row0 + 8) * N_DIM + col) = v1;
        }
    }
}

// ---------------- host-side NF5 table ----------------
// High-accuracy inverse normal CDF: Acklam rational approx + 2 Halley steps.
static double h_ninv(double p) {
    static const double a[6] = {-3.969683028665376e+01,  2.209460984245205e+02,
                                -2.759285104469687e+02,  1.383577518672690e+02,
                                -3.066479806614716e+01,  2.506628277459239e+00};
    static const double b[5] = {-5.447609879822406e+01,  1.615858368580409e+02,
                                -1.556989798598866e+02,  6.680131188771972e+01,
                                -1.328068155288572e+01};
    static const double c[6] = {-7.784894002430293e-03, -3.223964580411365e-01,
                                -2.400758277161838e+00, -2.549732539343734e+00,
                                 4.374664141464968e+00,  2.938163982698783e+00};
    static const double d[4] = { 7.784695709041462e-03,  3.224671290700398e-01,
                                 2.445134137142996e+00,  3.754408661907416e+00};
    const double pl = 0.02425, ph = 1.0 - pl;
    double x;
    if (p < pl) {
        double q = sqrt(-2.0 * log(p));
        x = (((((c[0]*q+c[1])*q+c[2])*q+c[3])*q+c[4])*q+c[5]) /
            ((((d[0]*q+d[1])*q+d[2])*q+d[3])*q+1.0);
    } else if (p <= ph) {
        double q = p - 0.5, r = q*q;
        x = (((((a[0]*r+a[1])*r+a[2])*r+a[3])*r+a[4])*r+a[5])*q /
            (((((b[0]*r+b[1])*r+b[2])*r+b[3])*r+b[4])*r+1.0);
    } else {
        double q = sqrt(-2.0 * log(1.0 - p));
        x = -(((((c[0]*q+c[1])*q+c[2])*q+c[3])*q+c[4])*q+c[5]) /
             ((((d[0]*q+d[1])*q+d[2])*q+d[3])*q+1.0);
    }
    for (int i = 0; i < 2; i++) {   // Halley refinement
        double e = 0.5 * erfc(-x / 1.4142135623730951) - p;
        double u = e * 2.5066282746310002 * exp(0.5 * x * x);
        x = x - u / (1.0 + 0.5 * x * u);
    }
    return x;
}

static unsigned short h_f2bf(float f) {   // round-to-nearest-even
    uint32_t u; memcpy(&u, &f, 4);
    u += 0x7fffu + ((u >> 16) & 1u);
    return (unsigned short)(u >> 16);
}
static float h_bf2f(unsigned short s) {
    uint32_t u = (uint32_t)s << 16; float f; memcpy(&f, &u, 4); return f;
}

static void build_tab(NF5Tab* tb) {
    float tab[32];
    {
        double a0 = 1.0 - 0.9677083;
        double step = (0.5 - a0) / 16.0;
        float n0 = (float)h_ninv(a0);
        for (int i = 0; i < 16; i++)
            tab[i] = (float)h_ninv(a0 + step * (double)i) / (-n0);
    }
    tab[16] = 0.0f;
    {
        double b0 = 0.9677083;
        double step = (b0 - 0.5) / 15.0;
        float plast = (float)h_ninv(b0);
        for (int i = 1; i <= 15; i++)
            tab[16 + i] = (float)h_ninv(0.5 + step * (double)i) / plast;
    }
    for (int i = 0; i < 31; i++) tb->bnd[i] = (tab[i] + tab[i + 1]) * 0.5f;
    uint32_t inf = 0x7f800000u; memcpy(&tb->bnd[31], &inf, 4);
    for (int i = 0; i < 32; i++) {
        unsigned short lh = h_f2bf(tab[i]);
        unsigned short ll = h_f2bf(tab[i] - h_bf2f(lh));
        tb->prs[i] = (uint32_t)lh | ((uint32_t)ll << 16);
    }
}

// ---------------- launch ----------------
extern "C" void kernel_launch(void* const* d_in, const int* in_sizes, int n_in,
                              void* d_out, int out_size) {
    const float* x    = (const float*)d_in[0];
    const float* w    = (const float*)d_in[1];
    const float* bias = (const float*)d_in[2];
    float* out        = (float*)d_out;

    NF5Tab tb;
    build_tab(&tb);

    void *pxh, *pxl, *pwh, *pwl;
    cudaGetSymbolAddress(&pxh, g_xh);
    cudaGetSymbolAddress(&pxl, g_xl);
    cudaGetSymbolAddress(&pwh, g_wh);
    cudaGetSymbolAddress(&pwl, g_wl);

    const int n8x = (M_DIM * K_DIM) / 8;     // 4194304
    const int n8w = (N_DIM * K_DIM) / 8;     // 131072
    quant_kernel<<<4096, 256>>>(tb, (const float4*)x, (uint4*)pxh, (uint4*)pxl, n8x);
    quant_kernel<<<512, 256>>>(tb, (const float4*)w, (uint4*)pwh, (uint4*)pwl, n8w);

    cudaFuncSetAttribute(gemm_kernel,
                         cudaFuncAttributeMaxDynamicSharedMemorySize, SMEM_BYTES);
    dim3 grid(N_DIM / BN, M_DIM / BM);   // (4, 256) = 1024 CTAs
    gemm_kernel<<<grid, 512, SMEM_BYTES>>>(bias, out);
}

// round 16
// speedup vs baseline: 1.1856x; 1.1856x over previous
#include <cuda_runtime.h>
#include <cuda_bf16.h>
#include <stdint.h>
#include <math.h>
#include <string.h>

// ---------------- problem constants ----------------
#define M_DIM 32768
#define N_DIM 1024
#define K_DIM 1024

#define BM 128
#define BN 256
#define BK 64
#define STAGES 4
#define KT_TOTAL 48                        // 3 segments * (1024/64)
#define A_BYTES (BM * 128)                 // 16 KB
#define B_BYTES (BN * 128)                 // 32 KB
#define STAGE_BYTES (A_BYTES + B_BYTES)    // 48 KB
#define SMEM_BYTES (STAGES * STAGE_BYTES)  // 192 KB

// ---------------- scratch (static device allocations) ----------------
__device__ __nv_bfloat16 g_xh[(size_t)M_DIM * K_DIM];
__device__ __nv_bfloat16 g_xl[(size_t)M_DIM * K_DIM];
__device__ __nv_bfloat16 g_wh[(size_t)N_DIM * K_DIM];
__device__ __nv_bfloat16 g_wl[(size_t)N_DIM * K_DIM];

// NF5 tables, host-computed, passed by value (256 B kernel param)
struct NF5Tab {
    float    bnd[32];   // 31 boundaries + +inf guard
    uint32_t prs[32];   // per level: bf16(level) | bf16(level - bf16(level)) << 16
};

// ---------------- quantize (R12 inner loop; single launch for x and w) -------
// thread = 8 consecutive elems; 4-lane subgroup = one 32-elem block.
// Blocks [0, XBLK): x via 4 grid-stride passes. Blocks [XBLK, XBLK+WBLK): w in
// one pass. Uniform per-block path (no divergence); counts divide exactly so
// every lane iterates every pass (redux.sync full-group participation).
#define N8X (M_DIM * K_DIM / 8)            // 4194304
#define N8W (N_DIM * K_DIM / 8)            // 131072
#define XBLK 4096
#define WBLK 512

__global__ void __launch_bounds__(256)
quant_kernel(const NF5Tab tab,
             const float4* __restrict__ xin, uint4* __restrict__ xhi,
             uint4* __restrict__ xlo,
             const float4* __restrict__ win, uint4* __restrict__ whi,
             uint4* __restrict__ wlo) {
    __shared__ float sthr[1025];
    __shared__ uint32_t sprs[2050];         // [2*key + sel] -> lh | ll<<16 (bf16 bits)
    for (int j = threadIdx.x; j < 1025; j += blockDim.x) {
        float left = (float)j * (1.0f / 512.0f) - 1.0f;
        int idx0 = 0;
#pragma unroll
        for (int i = 0; i < 31; i++) idx0 += (tab.bnd[i] < left) ? 1 : 0;
        int idx1 = (idx0 < 31) ? idx0 + 1 : 31;
        sthr[j] = tab.bnd[idx0];
        sprs[2 * j]     = tab.prs[idx0];
        sprs[2 * j + 1] = tab.prs[idx1];
    }
    __syncthreads();

    const uint32_t gmask = 0xFu << (threadIdx.x & 28u);  // 4-lane group mask
    const bool isx = blockIdx.x < XBLK;
    const float4* in = isx ? xin : win;
    uint4* hi = isx ? xhi : whi;
    uint4* lo = isx ? xlo : wlo;
    const int base   = isx ? (blockIdx.x * 256 + threadIdx.x)
                           : ((blockIdx.x - XBLK) * 256 + threadIdx.x);
    const int nend   = isx ? N8X : N8W;
    const int stride = isx ? (XBLK * 256) : (WBLK * 256);

    for (int gid = base; gid < nend; gid += stride) {
        float4 v0 = __ldcs(in + 2 * (size_t)gid);
        float4 v1 = __ldcs(in + 2 * (size_t)gid + 1);
        float vv[8] = {v0.x, v0.y, v0.z, v0.w, v1.x, v1.y, v1.z, v1.w};
        // amax via uint-max on |bits| (positive floats order-isomorphic to uints)
        uint32_t ab = 0;
#pragma unroll
        for (int t = 0; t < 8; t++)
            ab = max(ab, __float_as_uint(vv[t]) & 0x7fffffffu);
        uint32_t rb;
        asm volatile("redux.sync.max.u32 %0, %1, %2;" : "=r"(rb) : "r"(ab), "r"(gmask));
        float am = fmaxf(__uint_as_float(rb), 1e-12f);
        // exact ceil(log2(am)) via exponent bits (am normal, positive)
        uint32_t amb = __float_as_uint(am);
        int E = (int)(amb >> 23) - 127;
        int ce = ((amb & 0x7fffffu) != 0u) ? E + 1 : E;
        float inv = __uint_as_float((uint32_t)(127 - ce) << 23);
        // power-of-2 scale as packed bf16x2 (exactly representable)
        uint32_t scb = (uint32_t)__bfloat16_as_ushort(
            __float2bfloat16(__uint_as_float((uint32_t)(ce + 127) << 23)));
        uint32_t scpack = scb | (scb << 16);

        uint32_t q[8];   // packed (h = low16, l = high16) per element
#pragma unroll
        for (int t = 0; t < 8; t++) {
            float nrm = vv[t] * inv;                       // exact (pow2)
            int key = (int)fmaf(nrm, 512.0f, 512.0f);      // == (nrm+1)*512 bit-exact
            int sel = (sthr[key] < nrm) ? 1 : 0;
            uint32_t pr = sprs[2 * key + sel];
            // level * scale in bf16x2: both mults exact (bf16 level x pow2 scale)
            asm("mul.bf16x2 %0, %1, %2;" : "=r"(q[t]) : "r"(pr), "r"(scpack));
        }
        uint4 hv, lv;
        asm("prmt.b32 %0, %1, %2, 0x5410;" : "=r"(hv.x) : "r"(q[0]), "r"(q[1]));
        asm("prmt.b32 %0, %1, %2, 0x5410;" : "=r"(hv.y) : "r"(q[2]), "r"(q[3]));
        asm("prmt.b32 %0, %1, %2, 0x5410;" : "=r"(hv.z) : "r"(q[4]), "r"(q[5]));
        asm("prmt.b32 %0, %1, %2, 0x5410;" : "=r"(hv.w) : "r"(q[6]), "r"(q[7]));
        asm("prmt.b32 %0, %1, %2, 0x7632;" : "=r"(lv.x) : "r"(q[0]), "r"(q[1]));
        asm("prmt.b32 %0, %1, %2, 0x7632;" : "=r"(lv.y) : "r"(q[2]), "r"(q[3]));
        asm("prmt.b32 %0, %1, %2, 0x7632;" : "=r"(lv.z) : "r"(q[4]), "r"(q[5]));
        asm("prmt.b32 %0, %1, %2, 0x7632;" : "=r"(lv.w) : "r"(q[6]), "r"(q[7]));
        __stcs(hi + gid, hv);
        __stcs(lo + gid, lv);
    }
}

// ---------------- GEMM (R12/R8 exactly: HMMA + ldmatrix + cp.async) ----------
// CTA 128x256, 8 warps of 64x64, BK=64, 4 stages (192 KB smem).
__device__ __forceinline__ uint32_t smem_u32(const void* p) {
    uint32_t a;
    asm("{ .reg .u64 t; cvta.to.shared.u64 t, %1; cvt.u32.u64 %0, t; }" : "=r"(a) : "l"(p));
    return a;
}
__device__ __forceinline__ void cpa16(uint32_t dst, const void* src) {
    asm volatile("cp.async.cg.shared.global [%0], [%1], 16;\n" :: "r"(dst), "l"(src));
}
__device__ __forceinline__ void ldsm4(uint32_t* r, uint32_t addr) {
    asm volatile("ldmatrix.sync.aligned.m8n8.x4.shared.b16 {%0,%1,%2,%3}, [%4];\n"
                 : "=r"(r[0]), "=r"(r[1]), "=r"(r[2]), "=r"(r[3]) : "r"(addr));
}

#define MMA_BF16(d, a0, a1, a2, a3, b0, b1)                                      \
    asm volatile(                                                                \
        "mma.sync.aligned.m16n8k16.row.col.f32.bf16.bf16.f32 "                   \
        "{%0,%1,%2,%3}, {%4,%5,%6,%7}, {%8,%9}, {%0,%1,%2,%3};\n"                \
        : "+f"(d[0]), "+f"(d[1]), "+f"(d[2]), "+f"(d[3])                         \
        : "r"(a0), "r"(a1), "r"(a2), "r"(a3), "r"(b0), "r"(b1))

__global__ void __launch_bounds__(256, 1)
gemm_kernel(const float* __restrict__ bias, float* __restrict__ out) {
    extern __shared__ __align__(1024) char smem[];
    const uint32_t sb = smem_u32(smem);
    const int tid  = threadIdx.x;
    const int lane = tid & 31, wid = tid >> 5;
    const int m0 = blockIdx.y * BM;
    const int n0 = blockIdx.x * BN;
    const int wm = (wid >> 2) * 64;     // warp m offset (2 warps in m)
    const int wn = (wid & 3) * 64;      // warp n offset (4 warps in n)
    const int l15 = lane & 15, lh4 = lane >> 4;

    float acc[4][8][4];
#pragma unroll
    for (int i = 0; i < 4; i++)
#pragma unroll
        for (int j = 0; j < 8; j++)
#pragma unroll
            for (int k = 0; k < 4; k++) acc[i][j][k] = 0.0f;

    uint32_t af[2][4][4], bf[2][4][4];   // double-buffered fragments

    // stage loader: 16B cp.async, XOR-swizzled 128B rows. One commit per call.
    auto load_stage = [&](int tile, int s) {
        const int seg = tile >> 4;
        const int k0  = (tile & 15) * 64;
        const __nv_bfloat16* Ab = (seg == 1) ? g_xl : g_xh;
        const __nv_bfloat16* Bb = (seg == 2) ? g_wl : g_wh;
        const uint32_t stA = sb + s * STAGE_BYTES;
        const uint32_t stB = stA + A_BYTES;
#pragma unroll
        for (int q = 0; q < 4; q++) {
            int idx = tid + q * 256;
            int row = idx >> 3, ch = idx & 7;
            int sw = ch ^ (row & 7);
            cpa16(stA + row * 128 + sw * 16,
                  Ab + (size_t)(m0 + row) * K_DIM + k0 + ch * 8);
        }
#pragma unroll
        for (int q = 0; q < 8; q++) {
            int idx = tid + q * 256;
            int row = idx >> 3, ch = idx & 7;
            int sw = ch ^ (row & 7);
            cpa16(stB + row * 128 + sw * 16,
                  Bb + (size_t)(n0 + row) * K_DIM + k0 + ch * 8);
        }
        asm volatile("cp.async.commit_group;\n" ::);
    };

    // fragment loader for one k16 slice (kf) of a stage
    auto ldsm_frags = [&](uint32_t (*A)[4], uint32_t (*B)[4], uint32_t stA, int kf) {
        const uint32_t stB = stA + A_BYTES;
        const int ch = kf * 2 + lh4;
#pragma unroll
        for (int mf = 0; mf < 4; mf++) {
            int row = wm + mf * 16 + l15;
            ldsm4(A[mf], stA + row * 128 + ((ch ^ (row & 7)) * 16));
        }
#pragma unroll
        for (int p = 0; p < 4; p++) {
            int row = wn + p * 16 + l15;
            ldsm4(B[p], stB + row * 128 + ((ch ^ (row & 7)) * 16));
        }
    };

    // prologue: stages 0,1,2 in flight; wait stage 0 landed; preload kf0 frags
    load_stage(0, 0);
    load_stage(1, 1);
    load_stage(2, 2);
    asm volatile("cp.async.wait_group 2;\n" ::);
    __syncthreads();
    ldsm_frags(af[0], bf[0], sb, 0);

#pragma unroll 1
    for (int t = 0; t < KT_TOTAL; t++) {
        const uint32_t stA = sb + (t & 3) * STAGE_BYTES;
#pragma unroll
        for (int kf = 0; kf < 4; kf++) {
            const int cur = kf & 1, nxt = cur ^ 1;
            if (kf < 3) {
                ldsm_frags(af[nxt], bf[nxt], stA, kf + 1);
            } else {
                // stage t+1 was committed two tiles ago -> wait is a no-op;
                // the newest group (t+2's load) may stay in flight.
                asm volatile("cp.async.wait_group 1;\n" ::);
                __syncthreads();
                int nt = t + 3;
                if (nt < KT_TOTAL) load_stage(nt, nt & 3);
                else asm volatile("cp.async.commit_group;\n" ::);
                if (t + 1 < KT_TOTAL)
                    ldsm_frags(af[nxt], bf[nxt],
                               sb + ((t + 1) & 3) * STAGE_BYTES, 0);
            }
#pragma unroll
            for (int mf = 0; mf < 4; mf++) {
#pragma unroll
                for (int nf = 0; nf < 8; nf++) {
                    uint32_t b0 = bf[cur][nf >> 1][nf & 1];
                    uint32_t b1 = bf[cur][nf >> 1][(nf & 1) + 2];
                    MMA_BF16(acc[mf][nf], af[cur][mf][0], af[cur][mf][1],
                             af[cur][mf][2], af[cur][mf][3], b0, b1);
                }
            }
        }
    }

    // epilogue: + bias, f32 out
    const int r  = lane >> 2;
    const int c2 = (lane & 3) * 2;
#pragma unroll
    for (int nf = 0; nf < 8; nf++) {
        int col = n0 + wn + nf * 8 + c2;
        float b0 = __ldg(bias + col);
        float b1 = __ldg(bias + col + 1);
#pragma unroll
        for (int mf = 0; mf < 4; mf++) {
            int row0 = m0 + wm + mf * 16 + r;
            float2 v0 = make_float2(acc[mf][nf][0] + b0, acc[mf][nf][1] + b1);
            float2 v1 = make_float2(acc[mf][nf][2] + b0, acc[mf][nf][3] + b1);
            *(float2*)(out + (size_t)row0 * N_DIM + col) = v0;
            *(float2*)(out + (size_t)(row0 + 8) * N_DIM + col) = v1;
        }
    }
}

// ---------------- host-side NF5 table ----------------
// High-accuracy inverse normal CDF: Acklam rational approx + 2 Halley steps.
static double h_ninv(double p) {
    static const double a[6] = {-3.969683028665376e+01,  2.209460984245205e+02,
                                -2.759285104469687e+02,  1.383577518672690e+02,
                                -3.066479806614716e+01,  2.506628277459239e+00};
    static const double b[5] = {-5.447609879822406e+01,  1.615858368580409e+02,
                                -1.556989798598866e+02,  6.680131188771972e+01,
                                -1.328068155288572e+01};
    static const double c[6] = {-7.784894002430293e-03, -3.223964580411365e-01,
                                -2.400758277161838e+00, -2.549732539343734e+00,
                                 4.374664141464968e+00,  2.938163982698783e+00};
    static const double d[4] = { 7.784695709041462e-03,  3.224671290700398e-01,
                                 2.445134137142996e+00,  3.754408661907416e+00};
    const double pl = 0.02425, ph = 1.0 - pl;
    double x;
    if (p < pl) {
        double q = sqrt(-2.0 * log(p));
        x = (((((c[0]*q+c[1])*q+c[2])*q+c[3])*q+c[4])*q+c[5]) /
            ((((d[0]*q+d[1])*q+d[2])*q+d[3])*q+1.0);
    } else if (p <= ph) {
        double q = p - 0.5, r = q*q;
        x = (((((a[0]*r+a[1])*r+a[2])*r+a[3])*r+a[4])*r+a[5])*q /
            (((((b[0]*r+b[1])*r+b[2])*r+b[3])*r+b[4])*r+1.0);
    } else {
        double q = sqrt(-2.0 * log(1.0 - p));
        x = -(((((c[0]*q+c[1])*q+c[2])*q+c[3])*q+c[4])*q+c[5]) /
             ((((d[0]*q+d[1])*q+d[2])*q+d[3])*q+1.0);
    }
    for (int i = 0; i < 2; i++) {   // Halley refinement
        double e = 0.5 * erfc(-x / 1.4142135623730951) - p;
        double u = e * 2.5066282746310002 * exp(0.5 * x * x);
        x = x - u / (1.0 + 0.5 * x * u);
    }
    return x;
}

static unsigned short h_f2bf(float f) {   // round-to-nearest-even
    uint32_t u; memcpy(&u, &f, 4);
    u += 0x7fffu + ((u >> 16) & 1u);
    return (unsigned short)(u >> 16);
}
static float h_bf2f(unsigned short s) {
    uint32_t u = (uint32_t)s << 16; float f; memcpy(&f, &u, 4); return f;
}

static void build_tab(NF5Tab* tb) {
    float tab[32];
    {
        double a0 = 1.0 - 0.9677083;
        double step = (0.5 - a0) / 16.0;
        float n0 = (float)h_ninv(a0);
        for (int i = 0; i < 16; i++)
            tab[i] = (float)h_ninv(a0 + step * (double)i) / (-n0);
    }
    tab[16] = 0.0f;
    {
        double b0 = 0.9677083;
        double step = (b0 - 0.5) / 15.0;
        float plast = (float)h_ninv(b0);
        for (int i = 1; i <= 15; i++)
            tab[16 + i] = (float)h_ninv(0.5 + step * (double)i) / plast;
    }
    for (int i = 0; i < 31; i++) tb->bnd[i] = (tab[i] + tab[i + 1]) * 0.5f;
    uint32_t inf = 0x7f800000u; memcpy(&tb->bnd[31], &inf, 4);
    for (int i = 0; i < 32; i++) {
        unsigned short lh = h_f2bf(tab[i]);
        unsigned short ll = h_f2bf(tab[i] - h_bf2f(lh));
        tb->prs[i] = (uint32_t)lh | ((uint32_t)ll << 16);
    }
}

// ---------------- launch ----------------
extern "C" void kernel_launch(void* const* d_in, const int* in_sizes, int n_in,
                              void* d_out, int out_size) {
    const float* x    = (const float*)d_in[0];
    const float* w    = (const float*)d_in[1];
    const float* bias = (const float*)d_in[2];
    float* out        = (float*)d_out;

    NF5Tab tb;
    build_tab(&tb);

    void *pxh, *pxl, *pwh, *pwl;
    cudaGetSymbolAddress(&pxh, g_xh);
    cudaGetSymbolAddress(&pxl, g_xl);
    cudaGetSymbolAddress(&pwh, g_wh);
    cudaGetSymbolAddress(&pwl, g_wl);

    quant_kernel<<<XBLK + WBLK, 256>>>(
        tb,
        (const float4*)x, (uint4*)pxh, (uint4*)pxl,
        (const float4*)w, (uint4*)pwh, (uint4*)pwl);

    cudaFuncSetAttribute(gemm_kernel,
                         cudaFuncAttributeMaxDynamicSharedMemorySize, SMEM_BYTES);
    dim3 grid(N_DIM / BN, M_DIM / BM);   // (4, 256) = 1024 CTAs
    gemm_kernel<<<grid, 256, SMEM_BYTES>>>(bias, out);
}